// round 2
// baseline (speedup 1.0000x reference)
#include <cuda_runtime.h>
#include <cuda_fp16.h>

// MedianFilterLoss: per-row segmented min-plus DP over runs of ones.
// zeros contribute softplus(x); runs<3 contribute softplus(-x) each;
// runs>=3 contribute min over a 3-state DP evaluated along the run.

#define T_LEN 16384
#define TILE  8192
#define NTH   256
#define CHUNK (TILE / NTH)   // 32
#define BIGV  1e30f

__device__ float g_partial[4096];

__device__ __forceinline__ int sidx(int p) { return p + (p >> 5); }

__device__ __forceinline__ void softplus_pair(float x, float& c0, float& c1) {
    float L = __logf(1.0f + __expf(-fabsf(x)));
    c0 = fmaxf(x, 0.0f) + L;    // softplus(x)
    c1 = fmaxf(-x, 0.0f) + L;   // softplus(-x)
}

__global__ void __launch_bounds__(NTH) mfl_main(const float* __restrict__ xg,
                                                const int* __restrict__ tg) {
    __shared__ unsigned int sc[TILE + (TILE >> 5)];  // packed half2(c0,c1), skewed
    __shared__ unsigned int tb[TILE >> 5];           // target bits
    __shared__ float wsum[NTH / 32];

    const int bid  = blockIdx.x;
    const int row  = bid >> 1;
    const int half = bid & 1;
    const int base = row * T_LEN + half * TILE;
    const int tid  = threadIdx.x;
    const int lane = tid & 31;
    const int wid  = tid >> 5;

    // ---- Phase 1: coalesced load, uniform softplus precompute ----
    const float4* xv = reinterpret_cast<const float4*>(xg + base);
#pragma unroll
    for (int k = 0; k < TILE / 4 / NTH; ++k) {       // 8 iters
        int i = k * NTH + tid;
        float4 v = xv[i];
        int p = i * 4;
        int b = sidx(p);                              // 4 elems share skew block
        float xs[4] = {v.x, v.y, v.z, v.w};
#pragma unroll
        for (int j = 0; j < 4; ++j) {
            float c0, c1;
            softplus_pair(xs[j], c0, c1);
            __half2 h = __floats2half2_rn(c0, c1);
            sc[b + j] = *reinterpret_cast<unsigned int*>(&h);
        }
    }
#pragma unroll
    for (int k = 0; k < TILE / NTH; ++k) {           // 32 iters, coalesced
        int i = k * NTH + tid;
        unsigned int m = __ballot_sync(0xFFFFFFFFu, tg[base + i] != 0);
        if (lane == 0) tb[i >> 5] = m;
    }
    __syncthreads();

    // ---- Phase 2: per-thread chunk, run-owner DP ----
    float acc = 0.0f;
    const int s    = tid * CHUNK;
    const int send = s + CHUNK;
    int p = s;
    while (p < send) {
        if (!((tb[p >> 5] >> (p & 31)) & 1u)) {      // target == 0
            unsigned int u = sc[sidx(p)];
            __half2 h = *reinterpret_cast<__half2*>(&u);
            acc += __low2float(h);                    // c0
            ++p;
            continue;
        }
        // target == 1: am I the run start?
        bool is_start;
        if (p > 0) {
            is_start = !((tb[(p - 1) >> 5] >> ((p - 1) & 31)) & 1u);
        } else {
            is_start = (half == 0) ? true : (tg[base - 1] == 0);
        }
        if (!is_start) {                              // prefix of a run owned earlier
            do { ++p; } while (p < send && ((tb[p >> 5] >> (p & 31)) & 1u));
            continue;
        }
        // Own this run: walk it to its end (possibly beyond tile for half==0).
        float d1 = BIGV, d2 = BIGV, d3 = 0.0f, s1 = 0.0f;
        int len = 0;
        int q = p;
        while (q < TILE && ((tb[q >> 5] >> (q & 31)) & 1u)) {
            unsigned int u = sc[sidx(q)];
            __half2 h = *reinterpret_cast<__half2*>(&u);
            float c0 = __low2float(h), c1 = __high2float(h);
            float n1 = d2 + c1;
            float n2 = d3 + c0;
            float n3 = fminf(d1, d3) + c1;
            d1 = fminf(n1, BIGV); d2 = fminf(n2, BIGV); d3 = fminf(n3, BIGV);
            s1 += c1; ++len; ++q;
        }
        if (q == TILE && half == 0) {                 // run crosses mid-row boundary
            int g = base + TILE;
            const int gend = row * T_LEN + T_LEN;
            while (g < gend && tg[g] != 0) {
                float x = xg[g];
                float c0, c1;
                softplus_pair(x, c0, c1);
                float n1 = d2 + c1;
                float n2 = d3 + c0;
                float n3 = fminf(d1, d3) + c1;
                d1 = fminf(n1, BIGV); d2 = fminf(n2, BIGV); d3 = fminf(n3, BIGV);
                s1 += c1; ++len; ++g;
            }
        }
        acc += (len >= 3) ? fminf(fminf(d1, d2), d3) : s1;
        p = q;                                        // >= send if run left chunk
    }

    // ---- block reduction ----
#pragma unroll
    for (int off = 16; off; off >>= 1)
        acc += __shfl_down_sync(0xFFFFFFFFu, acc, off);
    if (lane == 0) wsum[wid] = acc;
    __syncthreads();
    if (wid == 0) {
        float v = (lane < NTH / 32) ? wsum[lane] : 0.0f;
#pragma unroll
        for (int off = 4; off; off >>= 1)
            v += __shfl_down_sync(0xFFFFFFFFu, v, off);
        if (lane == 0) g_partial[bid] = v;
    }
}

__global__ void mfl_final(float* __restrict__ o, int nparts, double inv_n) {
    __shared__ double sd[256];
    double s = 0.0;
    for (int i = threadIdx.x; i < nparts; i += 256)
        s += (double)g_partial[i];
    sd[threadIdx.x] = s;
    __syncthreads();
#pragma unroll
    for (int off = 128; off; off >>= 1) {
        if (threadIdx.x < off) sd[threadIdx.x] += sd[threadIdx.x + off];
        __syncthreads();
    }
    if (threadIdx.x == 0) o[0] = (float)(sd[0] * inv_n);
}

extern "C" void kernel_launch(void* const* d_in, const int* in_sizes, int n_in,
                              void* d_out, int out_size) {
    const float* xg = (const float*)d_in[0];
    const int*   tg = (const int*)d_in[1];
    long long n = (long long)in_sizes[0];      // 1024 * 16384
    int grid = (int)(n / TILE);                // 2048
    mfl_main<<<grid, NTH>>>(xg, tg);
    mfl_final<<<1, 256>>>((float*)d_out, grid, 1.0 / (double)n);
}

// round 3
// speedup vs baseline: 3.7248x; 3.7248x over previous
#include <cuda_runtime.h>
#include <cuda_fp16.h>

// MedianFilterLoss, decomposed:
//   loss = sum_i softplus((1-2*t_i)*x_i)                      (base, elementwise)
//        - sum_{runs of ones, len>=3} max-weight subset of w_i=relu(-x_i)
//          with pairwise distance >= 3 (3-state max-plus DP per run)
// Runs < 3 are forced all-ones => base only. Correction runs are enumerated
// via per-thread 32-bit masks; runs with no negative x are skipped (m = 0).

#define T_LEN 16384
#define TILE  8192
#define NTH   256
#define NWORDS (TILE / 32)   // 256 = one word per thread

__device__ float g_partial[2048];
__device__ unsigned int g_done;   // zero at start; reset by last block each launch

__device__ __forceinline__ float softplus_f(float z) {
    return fmaxf(z, 0.0f) + __logf(1.0f + __expf(-fabsf(z)));
}

__global__ void __launch_bounds__(NTH) mfl_fused(const float* __restrict__ xg,
                                                 const int* __restrict__ tg,
                                                 float* __restrict__ o,
                                                 double inv_n) {
    __shared__ __half sw[TILE];              // w = relu(-x), half
    __shared__ unsigned char tn[TILE / 4];   // nibble: t bits | neg bits<<4
    __shared__ unsigned int tbs[NWORDS];     // target bit words
    __shared__ unsigned int nbs[NWORDS];     // negative-x bit words
    __shared__ float wsum[NTH / 32];
    __shared__ double sdbl[NTH];
    __shared__ unsigned int s_last;

    const int bid  = blockIdx.x;
    const int row  = bid >> 1;
    const int half = bid & 1;
    const int base = row * T_LEN + half * TILE;
    const int tid  = threadIdx.x;
    const int lane = tid & 31;
    const int wid  = tid >> 5;

    // ---- Phase 1: coalesced load; base loss in registers; stage w + masks ----
    float acc = 0.0f;
    const float4* xv = reinterpret_cast<const float4*>(xg + base);
    const int4*   tv = reinterpret_cast<const int4*>(tg + base);
#pragma unroll
    for (int k = 0; k < TILE / 4 / NTH; ++k) {        // 8 iters
        int i = k * NTH + tid;
        float4 v  = xv[i];
        int4   t4 = tv[i];
        float xs[4] = {v.x, v.y, v.z, v.w};
        int   ts[4] = {t4.x, t4.y, t4.z, t4.w};
        unsigned nib = 0;
#pragma unroll
        for (int j = 0; j < 4; ++j) {
            float x = xs[j];
            bool one = (ts[j] != 0);
            acc += softplus_f(one ? -x : x);
            if (one)       nib |= 1u << j;
            if (x < 0.0f)  nib |= 1u << (4 + j);
        }
        __half2 h0 = __floats2half2_rn(fmaxf(-v.x, 0.0f), fmaxf(-v.y, 0.0f));
        __half2 h1 = __floats2half2_rn(fmaxf(-v.z, 0.0f), fmaxf(-v.w, 0.0f));
        reinterpret_cast<__half2*>(sw)[i * 2]     = h0;
        reinterpret_cast<__half2*>(sw)[i * 2 + 1] = h1;
        tn[i] = (unsigned char)nib;
    }
    __syncthreads();

    // ---- Phase 1.5: pack nibbles into 32-bit words (one word per thread) ----
    unsigned tw = 0, nw = 0;
    {
        const unsigned char* tp = tn + tid * 8;
#pragma unroll
        for (int j = 0; j < 8; ++j) {
            unsigned b = tp[j];
            tw |= (b & 0xFu) << (4 * j);
            nw |= (b >> 4)   << (4 * j);
        }
        tbs[tid] = tw;
        nbs[tid] = nw;
    }
    __syncthreads();

    // ---- Phase 2: enumerate owned runs via bit ops; DP only where needed ----
    bool prevbit;
    if (tid > 0) prevbit = (tbs[tid - 1] >> 31) & 1u;
    else         prevbit = half ? (tg[base - 1] != 0) : false;

    unsigned t = tw;
    if (prevbit) {                           // clear continuation run at bit 0
        unsigned im = ~t;
        if (im == 0u) t = 0u;
        else {
            int c = __ffs(im) - 1;           // trailing ones count (0 if bit0==0)
            if (c > 0) t &= ~((1u << c) - 1u);
        }
    }

    while (t) {
        int s = __ffs(t) - 1;
        int p = (tid << 5) + s;
        // scan run extent + neg presence
        int e = p;
        bool hasneg = false;
        {
            int wi = tid, bo = s;
            for (;;) {
                unsigned m  = tbs[wi] >> bo;
                unsigned im = ~m;
                int c = im ? (__ffs(im) - 1) : (32 - bo);
                unsigned ones = (c >= 32) ? 0xFFFFFFFFu : ((1u << c) - 1u);
                hasneg |= (nbs[wi] & (ones << bo)) != 0u;
                e += c;
                if (bo + c < 32) break;      // run ended mid-word
                ++wi; bo = 0;
                if (wi == NWORDS) break;     // run reached tile end
                if (!(tbs[wi] & 1u)) break;  // ended exactly at word boundary
            }
        }
        int len = e - p;
        bool spill = (e == TILE) && (half == 0);
        if ((len >= 3 && hasneg) || spill) {
            float m0 = 0.0f, m1 = 0.0f, m2 = 0.0f;
            for (int q = p; q < e; ++q) {
                float wv = __half2float(sw[q]);
                float mi = fmaxf(m2, m0 + wv);
                m0 = m1; m1 = m2; m2 = mi;
            }
            if (spill) {                     // run crosses mid-row tile boundary
                int g = base + TILE;
                const int gend = row * T_LEN + T_LEN;
                while (g < gend && tg[g] != 0) {
                    float wv = fmaxf(-xg[g], 0.0f);
                    float mi = fmaxf(m2, m0 + wv);
                    m0 = m1; m1 = m2; m2 = mi;
                    ++len; ++g;
                }
            }
            if (len >= 3) acc -= m2;
        }
        // clear processed run bits from t (bits below s already clear)
        int eb = e - (tid << 5);
        if (eb >= 32) t = 0u;
        else          t &= ~((1u << eb) - 1u);
    }

    // ---- block reduction ----
#pragma unroll
    for (int off = 16; off; off >>= 1)
        acc += __shfl_down_sync(0xFFFFFFFFu, acc, off);
    if (lane == 0) wsum[wid] = acc;
    __syncthreads();
    float blocksum = 0.0f;
    if (wid == 0) {
        float v = (lane < NTH / 32) ? wsum[lane] : 0.0f;
#pragma unroll
        for (int off = 4; off; off >>= 1)
            v += __shfl_down_sync(0xFFFFFFFFu, v, off);
        blocksum = v;
    }

    // ---- last-block-done final reduction (no second launch) ----
    if (tid == 0) {
        g_partial[bid] = blocksum;
        __threadfence();
        unsigned old = atomicAdd(&g_done, 1u);
        s_last = (old == gridDim.x - 1) ? 1u : 0u;
    }
    __syncthreads();
    if (s_last) {
        const volatile float* gp = g_partial;
        double sv = 0.0;
        for (int i = tid; i < (int)gridDim.x; i += NTH)
            sv += (double)gp[i];
        sdbl[tid] = sv;
        __syncthreads();
#pragma unroll
        for (int off = NTH / 2; off; off >>= 1) {
            if (tid < off) sdbl[tid] += sdbl[tid + off];
            __syncthreads();
        }
        if (tid == 0) {
            o[0] = (float)(sdbl[0] * inv_n);
            g_done = 0;                      // reset for next (graph) replay
        }
    }
}

extern "C" void kernel_launch(void* const* d_in, const int* in_sizes, int n_in,
                              void* d_out, int out_size) {
    const float* xg = (const float*)d_in[0];
    const int*   tg = (const int*)d_in[1];
    long long n = (long long)in_sizes[0];      // 1024 * 16384
    int grid = (int)(n / TILE);                // 2048
    mfl_fused<<<grid, NTH>>>(xg, tg, (float*)d_out, 1.0 / (double)n);
}

// round 4
// speedup vs baseline: 5.5394x; 1.4872x over previous
#include <cuda_runtime.h>
#include <cuda_fp16.h>

// MedianFilterLoss, decomposed:
//   loss = sum_i softplus((1-2*t_i)*x_i)                       (base, elementwise)
//        - sum_{runs of ones, len>=3} max-weight subset of w_i = relu(-x_i)
//          with pairwise distance >= 3 (3-state max-plus DP per run)
// Shared encoding: one half per element, = relu(-x) if t==1, else -1.0 (sign = t bit).
// Phase 2 is a convergent 32-step predicated DP per thread over its contiguous chunk;
// cross-thread runs: prefix skipped via inPrefix predicate, suffix walked by owner.

#define T_LEN 16384
#define TILE  8192
#define NTH   256
#define ROWH  40          // halves per thread-row (32 data + 8 pad) = 80B, 16B-aligned

__device__ float g_partial[2048];
__device__ unsigned int g_done;

__global__ void __launch_bounds__(NTH) mfl_fused(const float* __restrict__ xg,
                                                 const int* __restrict__ tg,
                                                 float* __restrict__ o,
                                                 double inv_n) {
    __shared__ __half sw[NTH * ROWH];
    __shared__ float wsum[NTH / 32];
    __shared__ double sdbl[NTH];
    __shared__ unsigned int s_last;

    const int bid  = blockIdx.x;
    const int row  = bid >> 1;
    const int half = bid & 1;
    const int base = row * T_LEN + half * TILE;
    const int tid  = threadIdx.x;
    const int lane = tid & 31;
    const int wid  = tid >> 5;

    // ---- Phase 1: coalesced load; fp32 base loss; stage sign-encoded w ----
    float acc = 0.0f;
    const float4* xv = reinterpret_cast<const float4*>(xg + base);
    const int4*   tv = reinterpret_cast<const int4*>(tg + base);
#pragma unroll
    for (int k = 0; k < TILE / 4 / NTH; ++k) {        // 8 iters
        int i = k * NTH + tid;
        float4 v  = xv[i];
        int4   t4 = tv[i];
        float xs[4] = {v.x, v.y, v.z, v.w};
        int   ts[4] = {t4.x, t4.y, t4.z, t4.w};
        float enc[4];
#pragma unroll
        for (int j = 0; j < 4; ++j) {
            float x  = xs[j];
            bool one = (ts[j] != 0);
            float L  = __logf(1.0f + __expf(-fabsf(x)));   // target-independent
            float r0 = fmaxf(x, 0.0f);
            float r1 = fmaxf(-x, 0.0f);
            acc += (one ? r1 : r0) + L;
            enc[j] = one ? r1 : -1.0f;
        }
        __half2 h0 = __floats2half2_rn(enc[0], enc[1]);
        __half2 h1 = __floats2half2_rn(enc[2], enc[3]);
        // group i covers elements 4i..4i+3 -> row i>>3, col (i&7)*4
        unsigned r = (unsigned)(i >> 3);
        unsigned c = (unsigned)(i & 7) * 4u;
        uint2 pk;
        pk.x = *reinterpret_cast<unsigned int*>(&h0);
        pk.y = *reinterpret_cast<unsigned int*>(&h1);
        *reinterpret_cast<uint2*>(&sw[r * ROWH + c]) = pk;
    }
    __syncthreads();

    // ---- Phase 2: convergent per-thread DP over 32 contiguous elements ----
    bool inPref;
    if (tid == 0) inPref = half ? (tg[base - 1] != 0) : false;
    else          inPref = (__half2float(sw[(tid - 1) * ROWH + 31]) >= 0.0f);

    float m0 = 0.0f, m1 = 0.0f, m2 = 0.0f;
    int len = 0;
    const unsigned bh = (unsigned)tid * ROWH;
#pragma unroll
    for (int c = 0; c < 4; ++c) {
        uint4 q = *reinterpret_cast<const uint4*>(&sw[bh + c * 8]);
        unsigned ws[4] = {q.x, q.y, q.z, q.w};
#pragma unroll
        for (int u = 0; u < 4; ++u) {
            __half2 hh = *reinterpret_cast<__half2*>(&ws[u]);
            float2 f2 = __half22float2(hh);
            float fv[2] = {f2.x, f2.y};
#pragma unroll
            for (int e = 0; e < 2; ++e) {
                float f = fv[e];
                bool b = (f >= 0.0f);
                inPref = inPref && b;
                bool bb = b && !inPref;
                float nm2 = fmaxf(m2, m0 + f);
                if (!bb && len >= 3) acc -= m2;      // close local run
                m0 = bb ? m1 : 0.0f;
                m1 = bb ? m2 : 0.0f;
                m2 = bb ? nm2 : 0.0f;
                len = bb ? len + 1 : 0;
            }
        }
    }

    // ---- suffix run: owner walks forward (rare, short) ----
    if (len > 0) {
        int p = (tid + 1) * 32;
        for (;;) {
            if (p >= TILE) {
                if (half == 0) {                      // spill across mid-row boundary
                    int g = base + TILE;
                    const int gend = row * T_LEN + T_LEN;
                    while (g < gend && tg[g] != 0) {
                        float w = fmaxf(-xg[g], 0.0f);
                        float nm = fmaxf(m2, m0 + w);
                        m0 = m1; m1 = m2; m2 = nm; ++len; ++g;
                    }
                }
                break;
            }
            float v = __half2float(sw[(p >> 5) * ROWH + (p & 31)]);
            if (v < 0.0f) break;
            float nm = fmaxf(m2, m0 + v);
            m0 = m1; m1 = m2; m2 = nm; ++len; ++p;
        }
        if (len >= 3) acc -= m2;
    }

    // ---- block reduction ----
#pragma unroll
    for (int off = 16; off; off >>= 1)
        acc += __shfl_down_sync(0xFFFFFFFFu, acc, off);
    if (lane == 0) wsum[wid] = acc;
    __syncthreads();
    float blocksum = 0.0f;
    if (wid == 0) {
        float v = (lane < NTH / 32) ? wsum[lane] : 0.0f;
#pragma unroll
        for (int off = 4; off; off >>= 1)
            v += __shfl_down_sync(0xFFFFFFFFu, v, off);
        blocksum = v;
    }

    // ---- last-block-done final reduction (single launch) ----
    if (tid == 0) {
        g_partial[bid] = blocksum;
        __threadfence();
        unsigned old = atomicAdd(&g_done, 1u);
        s_last = (old == gridDim.x - 1) ? 1u : 0u;
    }
    __syncthreads();
    if (s_last) {
        const volatile float* gp = g_partial;
        double sv = 0.0;
        for (int i = tid; i < (int)gridDim.x; i += NTH)
            sv += (double)gp[i];
        sdbl[tid] = sv;
        __syncthreads();
#pragma unroll
        for (int off = NTH / 2; off; off >>= 1) {
            if (tid < off) sdbl[tid] += sdbl[tid + off];
            __syncthreads();
        }
        if (tid == 0) {
            o[0] = (float)(sdbl[0] * inv_n);
            g_done = 0;                               // reset for next graph replay
        }
    }
}

extern "C" void kernel_launch(void* const* d_in, const int* in_sizes, int n_in,
                              void* d_out, int out_size) {
    const float* xg = (const float*)d_in[0];
    const int*   tg = (const int*)d_in[1];
    long long n = (long long)in_sizes[0];      // 1024 * 16384
    int grid = (int)(n / TILE);                // 2048
    mfl_fused<<<grid, NTH>>>(xg, tg, (float*)d_out, 1.0 / (double)n);
}